// round 3
// baseline (speedup 1.0000x reference)
#include <cuda_runtime.h>

#define DIMC 1024
#define NHEAD 16
#define HDIM 64
#define BATCH 4
#define SEQ 2048
#define MTOT (BATCH*SEQ)
#define NQKV (3*DIMC)

__device__ float g_qkv[(size_t)3*BATCH*NHEAD*SEQ*HDIM];   // [3][B][H][S][D]
__device__ float g_attn[(size_t)MTOT*DIMC];               // [B*S][C]

__device__ __forceinline__ unsigned f2tf(float x){
    unsigned r; asm("cvt.rna.tf32.f32 %0,%1;" : "=r"(r) : "f"(x)); return r;
}

__device__ __forceinline__ void mma8(float* c, const unsigned* a, const unsigned* b){
    asm volatile(
      "mma.sync.aligned.m16n8k8.row.col.f32.tf32.tf32.f32 "
      "{%0,%1,%2,%3},{%4,%5,%6,%7},{%8,%9},{%0,%1,%2,%3};\n"
      : "+f"(c[0]),"+f"(c[1]),"+f"(c[2]),"+f"(c[3])
      : "r"(a[0]),"r"(a[1]),"r"(a[2]),"r"(a[3]),"r"(b[0]),"r"(b[1]));
}

// ---------------------------------------------------------------------------
// Fragment-packed tensor-core GEMM: C = A[M,1024] @ B[1024,N] + bias
// A smem layout: addr(k,m) = k*132 + (m&15)*8 + (m>>4)   (k in 0..15)
//   -> one LDS.128 fetches a-frag slot s for 4 consecutive m-tiles
// B smem layout: addr(k,n) = k*132 + (n&7)*16 + (n>>3)
//   -> one LDS.128 fetches b-frag slot s for 4 consecutive n-tiles
// ---------------------------------------------------------------------------
#define GSTR 132

template<int N, bool SCATTER>
__global__ __launch_bounds__(256)
void gemm_mma(const float* __restrict__ A, const float* __restrict__ B,
              const float* __restrict__ bias, float* __restrict__ out)
{
    __shared__ __align__(16) unsigned As[2][16*GSTR];
    __shared__ __align__(16) unsigned Bs[2][16*GSTR];
    const int tid=threadIdx.x, lane=tid&31, warp=tid>>5;
    const int g=lane>>2, tg=lane&3;
    const int mtb=(warp>>2)*4, ntb=(warp&3)*4;       // tile bases
    const int bm=blockIdx.y*128, bn=blockIdx.x*128;
    const float* Ab = (SCATTER ? A : (const float*)g_attn) + (size_t)bm*DIMC;
    const float* Bb = B + bn;

    float4 ar[2], br[2];
    float acc[4][4][4];
    #pragma unroll
    for(int i=0;i<4;i++)
      #pragma unroll
      for(int j=0;j<4;j++)
        #pragma unroll
        for(int k=0;k<4;k++) acc[i][j][k]=0.f;

    // tile-0 prologue
    #pragma unroll
    for(int i=0;i<2;i++){
        int idx=tid+(i<<8);
        ar[i]=*(const float4*)(Ab + (size_t)(idx>>2)*DIMC + ((idx&3)<<2));
        br[i]=*(const float4*)(Bb + (size_t)(idx>>5)*N + ((idx&31)<<2));
    }
    #pragma unroll
    for(int i=0;i<2;i++){
        int idx=tid+(i<<8);
        int r=idx>>2, kc=(idx&3)<<2, rot=idx&3;
        const float* av=&ar[i].x;
        #pragma unroll
        for(int jj=0;jj<4;jj++){
            int j=(jj+rot)&3;
            As[0][(kc+j)*GSTR + (r&15)*8 + (r>>4)] = f2tf(av[j]);
        }
        int rowb=idx>>5, nc=(idx&31)<<2;
        const float* bv=&br[i].x;
        #pragma unroll
        for(int j=0;j<4;j++)
            Bs[0][rowb*GSTR + ((nc&7)+j)*16 + (nc>>3)] = f2tf(bv[j]);
    }
    __syncthreads();

    const int NT = DIMC/16;
    for(int kt=0;kt<NT;kt++){
        const int buf=kt&1;
        if(kt<NT-1){
            #pragma unroll
            for(int i=0;i<2;i++){
                int idx=tid+(i<<8);
                ar[i]=*(const float4*)(Ab + (size_t)(idx>>2)*DIMC + (kt+1)*16 + ((idx&3)<<2));
                br[i]=*(const float4*)(Bb + (size_t)((kt+1)*16+(idx>>5))*N + ((idx&31)<<2));
            }
        }
        #pragma unroll
        for(int ks=0;ks<2;ks++){
            const unsigned* Ap=&As[buf][(ks*8+tg)*GSTR + g*8 + mtb];
            uint4 a0=*(const uint4*)Ap;
            uint4 a1=*(const uint4*)(Ap+64);
            uint4 a2=*(const uint4*)(Ap+4*GSTR);
            uint4 a3=*(const uint4*)(Ap+4*GSTR+64);
            const unsigned* Bp=&Bs[buf][(ks*8+tg)*GSTR + g*16 + ntb];
            uint4 b0=*(const uint4*)Bp;
            uint4 b1=*(const uint4*)(Bp+4*GSTR);
            const unsigned* A0=(const unsigned*)&a0;
            const unsigned* A1=(const unsigned*)&a1;
            const unsigned* A2=(const unsigned*)&a2;
            const unsigned* A3=(const unsigned*)&a3;
            const unsigned* B0=(const unsigned*)&b0;
            const unsigned* B1=(const unsigned*)&b1;
            #pragma unroll
            for(int mi=0;mi<4;mi++){
                unsigned afr[4]={A0[mi],A1[mi],A2[mi],A3[mi]};
                #pragma unroll
                for(int ni=0;ni<4;ni++){
                    unsigned bfr[2]={B0[ni],B1[ni]};
                    mma8(acc[mi][ni],afr,bfr);
                }
            }
        }
        if(kt<NT-1){
            #pragma unroll
            for(int i=0;i<2;i++){
                int idx=tid+(i<<8);
                int r=idx>>2, kc=(idx&3)<<2, rot=idx&3;
                const float* av=&ar[i].x;
                #pragma unroll
                for(int jj=0;jj<4;jj++){
                    int j=(jj+rot)&3;
                    As[buf^1][(kc+j)*GSTR + (r&15)*8 + (r>>4)] = f2tf(av[j]);
                }
                int rowb=idx>>5, nc=(idx&31)<<2;
                const float* bv=&br[i].x;
                #pragma unroll
                for(int j=0;j<4;j++)
                    Bs[buf^1][rowb*GSTR + ((nc&7)+j)*16 + (nc>>3)] = f2tf(bv[j]);
            }
        }
        __syncthreads();
    }

    #pragma unroll
    for(int mi=0;mi<4;mi++){
        #pragma unroll
        for(int ni=0;ni<4;ni++){
            #pragma unroll
            for(int e=0;e<4;e++){
                const int r = bm + (mtb+mi)*16 + g + ((e>=2)?8:0);
                const int c = bn + (ntb+ni)*8 + 2*tg + (e&1);
                const float v = acc[mi][ni][e] + bias[c];
                if(SCATTER){
                    const int b=r>>11, s=r&2047;
                    const int t=c>>10, h=(c>>6)&15, d=c&63;
                    g_qkv[((((size_t)t*BATCH+b)*NHEAD+h)*SEQ+s)*HDIM+d]=v;
                } else {
                    out[(size_t)r*N+c]=v;
                }
            }
        }
    }
}

// ---------------------------------------------------------------------------
// Flash attention. Q held in registers as mma fragments (loaded once via a
// staged pass through the P buffer). K/V fragment-packed:
//   K: addr(key,d) = d*68 + (key&7)*8 + (key>>3)
//   V: addr(key,d) = key*68 + (d&7)*8 + (d>>3)
// P: per-warp A-fragment layout: wbase + (kst*32+lane)*4 + slot
// ---------------------------------------------------------------------------
#define QKOFF ((size_t)BATCH*NHEAD*SEQ*HDIM)
#define KSTR 68

__global__ __launch_bounds__(128)
void flash_mma()
{
    extern __shared__ __align__(16) unsigned sm[];
    unsigned* Ks=sm;                 // 4352 words
    unsigned* Vs=sm+64*KSTR;         // 4352 words
    unsigned* Ps=sm+2*64*KSTR;       // 4096 words (also Q staging)
    const int tid=threadIdx.x, lane=tid&31, warp=tid>>5;
    const int g=lane>>2, tg=lane&3;
    const int b=blockIdx.y>>4, h=blockIdx.y&15;
    const int q0=blockIdx.x*64;
    const float* Qg=g_qkv + ((size_t)(b*NHEAD+h))*SEQ*HDIM;
    const float* Kg=Qg + QKOFF;
    const float* Vg=Kg + QKOFF;
    unsigned* Pw = Ps + warp*1024;

    // stage Q into fragment layout, then pull into registers
    #pragma unroll
    for(int i=0;i<8;i++){
        int idx=tid+(i<<7);
        int r=idx>>4, c4=(idx&15)<<2;
        float4 q4=*(const float4*)(Qg+(size_t)(q0+r)*HDIM+c4);
        const float* qv=&q4.x;
        unsigned* dst=&Ps[(r>>4)*1024 + ((c4>>3)*32 + (r&7)*4)*4 + ((r>>3)&1) + 2*((c4>>2)&1)];
        #pragma unroll
        for(int j=0;j<4;j++) dst[j*4]=f2tf(qv[j]);
    }
    __syncthreads();
    uint4 q_all[8];
    #pragma unroll
    for(int ks=0;ks<8;ks++)
        q_all[ks]=*(const uint4*)&Pw[ks*128 + lane*4];

    float oc[8][4];
    #pragma unroll
    for(int i=0;i<8;i++)
        #pragma unroll
        for(int j=0;j<4;j++) oc[i][j]=0.f;
    float m0=-1e30f, m1=-1e30f, l0=0.f, l1=0.f;
    const float scale=0.125f;

    for(int kt=0;kt<SEQ/64;kt++){
        __syncthreads();   // all warps done with prev K/V (and Q staging on iter 0)
        #pragma unroll
        for(int i=0;i<8;i++){
            int idx=tid+(i<<7);
            int r=idx>>4, c4=(idx&15)<<2;
            float4 k4=*(const float4*)(Kg+(size_t)(kt*64+r)*HDIM+c4);
            float4 v4=*(const float4*)(Vg+(size_t)(kt*64+r)*HDIM+c4);
            const float* kv=&k4.x;
            const float* vv=&v4.x;
            int rot=idx&15;
            #pragma unroll
            for(int jj=0;jj<4;jj++){
                int j=(jj+rot)&3;
                Ks[(c4+j)*KSTR + (r&7)*8 + (r>>3)] = f2tf(kv[j]);
            }
            #pragma unroll
            for(int j=0;j<4;j++)
                Vs[r*KSTR + ((c4&7)+j)*8 + (c4>>3)] = f2tf(vv[j]);
        }
        __syncthreads();

        // S = Q @ K^T
        float sc[8][4];
        #pragma unroll
        for(int i=0;i<8;i++)
            #pragma unroll
            for(int j=0;j<4;j++) sc[i][j]=0.f;
        #pragma unroll
        for(int ks=0;ks<8;ks++){
            const unsigned* kb=&Ks[(ks*8+tg)*KSTR + g*8];
            uint4 b00=*(const uint4*)kb;
            uint4 b01=*(const uint4*)(kb+4);
            uint4 b10=*(const uint4*)(kb+4*KSTR);
            uint4 b11=*(const uint4*)(kb+4*KSTR+4);
            const unsigned* aq=(const unsigned*)&q_all[ks];
            const unsigned* B00=(const unsigned*)&b00;
            const unsigned* B01=(const unsigned*)&b01;
            const unsigned* B10=(const unsigned*)&b10;
            const unsigned* B11=(const unsigned*)&b11;
            #pragma unroll
            for(int ni=0;ni<4;ni++){
                unsigned bfr[2]={B00[ni],B10[ni]};
                mma8(sc[ni],aq,bfr);
            }
            #pragma unroll
            for(int ni=0;ni<4;ni++){
                unsigned bfr[2]={B01[ni],B11[ni]};
                mma8(sc[ni+4],aq,bfr);
            }
        }

        // online softmax
        float mx0=-1e30f, mx1=-1e30f;
        #pragma unroll
        for(int ni=0;ni<8;ni++){
            sc[ni][0]*=scale; sc[ni][1]*=scale; sc[ni][2]*=scale; sc[ni][3]*=scale;
            mx0=fmaxf(mx0,fmaxf(sc[ni][0],sc[ni][1]));
            mx1=fmaxf(mx1,fmaxf(sc[ni][2],sc[ni][3]));
        }
        mx0=fmaxf(mx0,__shfl_xor_sync(0xffffffffu,mx0,1));
        mx0=fmaxf(mx0,__shfl_xor_sync(0xffffffffu,mx0,2));
        mx1=fmaxf(mx1,__shfl_xor_sync(0xffffffffu,mx1,1));
        mx1=fmaxf(mx1,__shfl_xor_sync(0xffffffffu,mx1,2));
        const float nm0=fmaxf(m0,mx0), nm1=fmaxf(m1,mx1);
        const float a0=__expf(m0-nm0), a1=__expf(m1-nm1);
        m0=nm0; m1=nm1;
        float s0=0.f, s1=0.f;
        #pragma unroll
        for(int ni=0;ni<8;ni++){
            sc[ni][0]=__expf(sc[ni][0]-nm0); sc[ni][1]=__expf(sc[ni][1]-nm0);
            sc[ni][2]=__expf(sc[ni][2]-nm1); sc[ni][3]=__expf(sc[ni][3]-nm1);
            s0+=sc[ni][0]+sc[ni][1];
            s1+=sc[ni][2]+sc[ni][3];
        }
        s0+=__shfl_xor_sync(0xffffffffu,s0,1); s0+=__shfl_xor_sync(0xffffffffu,s0,2);
        s1+=__shfl_xor_sync(0xffffffffu,s1,1); s1+=__shfl_xor_sync(0xffffffffu,s1,2);
        l0=l0*a0+s0; l1=l1*a1+s1;

        // P -> per-warp fragment buffer
        #pragma unroll
        for(int ni=0;ni<8;ni++){
            unsigned* pp=&Pw[(ni*32 + g*4 + ((2*tg)&3))*4 + 2*(tg>>1)];
            uint2 v0=make_uint2(f2tf(sc[ni][0]), f2tf(sc[ni][2]));
            uint2 v1=make_uint2(f2tf(sc[ni][1]), f2tf(sc[ni][3]));
            *(uint2*)pp=v0;
            *(uint2*)(pp+4)=v1;
        }
        __syncwarp();

        #pragma unroll
        for(int di=0;di<8;di++){
            oc[di][0]*=a0; oc[di][1]*=a0; oc[di][2]*=a1; oc[di][3]*=a1;
        }
        // O += P @ V
        #pragma unroll
        for(int ks=0;ks<8;ks++){
            uint4 af=*(const uint4*)&Pw[ks*128 + lane*4];
            const unsigned* vb=&Vs[(ks*8+tg)*KSTR + g*8];
            uint4 v00=*(const uint4*)vb;
            uint4 v01=*(const uint4*)(vb+4);
            uint4 v10=*(const uint4*)(vb+4*KSTR);
            uint4 v11=*(const uint4*)(vb+4*KSTR+4);
            const unsigned* AF=(const unsigned*)&af;
            const unsigned* V00=(const unsigned*)&v00;
            const unsigned* V01=(const unsigned*)&v01;
            const unsigned* V10=(const unsigned*)&v10;
            const unsigned* V11=(const unsigned*)&v11;
            #pragma unroll
            for(int di=0;di<4;di++){
                unsigned bfr[2]={V00[di],V10[di]};
                mma8(oc[di],AF,bfr);
            }
            #pragma unroll
            for(int di=0;di<4;di++){
                unsigned bfr[2]={V01[di],V11[di]};
                mma8(oc[di+4],AF,bfr);
            }
        }
        __syncwarp();   // P buffer reads done before next iteration overwrites
    }

    const float i0=1.f/l0, i1=1.f/l1;
    const int r0=q0+warp*16+g, r1=r0+8;
    float* O0=&g_attn[((size_t)(b*SEQ)+r0)*DIMC + h*HDIM];
    float* O1=&g_attn[((size_t)(b*SEQ)+r1)*DIMC + h*HDIM];
    #pragma unroll
    for(int di=0;di<8;di++){
        const int c=di*8+2*tg;
        *(float2*)&O0[c]=make_float2(oc[di][0]*i0, oc[di][1]*i0);
        *(float2*)&O1[c]=make_float2(oc[di][2]*i1, oc[di][3]*i1);
    }
}

// ---------------------------------------------------------------------------
extern "C" void kernel_launch(void* const* d_in, const int* in_sizes, int n_in,
                              void* d_out, int out_size)
{
    const float* x     = (const float*)d_in[0];
    const float* Wqkv  = (const float*)d_in[1];
    const float* bqkv  = (const float*)d_in[2];
    const float* Wproj = (const float*)d_in[3];
    const float* bproj = (const float*)d_in[4];
    float* out = (float*)d_out;

    const int flash_smem = (2*64*KSTR + 4*1024)*4;   // 51200 B
    cudaFuncSetAttribute(flash_mma, cudaFuncAttributeMaxDynamicSharedMemorySize, flash_smem);

    dim3 g1(NQKV/128, MTOT/128);   // (24, 64)
    gemm_mma<NQKV, true><<<g1, 256>>>(x, Wqkv, bqkv, nullptr);

    dim3 g2(SEQ/64, BATCH*NHEAD);  // (32, 64)
    flash_mma<<<g2, 128, flash_smem>>>();

    dim3 g3(DIMC/128, MTOT/128);   // (8, 64)
    gemm_mma<DIMC, false><<<g3, 256>>>(nullptr, Wproj, bproj, out);
}

// round 4
// speedup vs baseline: 1.4180x; 1.4180x over previous
#include <cuda_runtime.h>

#define DIMC 1024
#define NHEAD 16
#define HDIM 64
#define BATCH 4
#define SEQ 2048
#define MTOT (BATCH*SEQ)
#define NQKV (3*DIMC)

__device__ float g_qkv[(size_t)3*BATCH*NHEAD*SEQ*HDIM];   // [3][B][H][S][D]
__device__ float g_attn[(size_t)MTOT*DIMC];               // [B*S][C]

__device__ __forceinline__ unsigned f2tf(float x){
    unsigned r; asm("cvt.rna.tf32.f32 %0,%1;" : "=r"(r) : "f"(x)); return r;
}

__device__ __forceinline__ void mma8(float* c, const unsigned* a, const unsigned* b){
    asm volatile(
      "mma.sync.aligned.m16n8k8.row.col.f32.tf32.tf32.f32 "
      "{%0,%1,%2,%3},{%4,%5,%6,%7},{%8,%9},{%0,%1,%2,%3};\n"
      : "+f"(c[0]),"+f"(c[1]),"+f"(c[2]),"+f"(c[3])
      : "r"(a[0]),"r"(a[1]),"r"(a[2]),"r"(a[3]),"r"(b[0]),"r"(b[1]));
}

// ---------------------------------------------------------------------------
// GEMM: C = A[M,1024] @ B[1024,N] + bias.  128x128x16 tiles, double-buffered.
// As: [m][k] stride 40 (40%32==8): frag loads bank 8g+tg (conflict-free),
//     stores are STS.128 of 4 consecutive k (<=2-way).
// Bs: [k][n] stride 136 (8k+n conflict-free loads), STS.128 stores clean.
// ---------------------------------------------------------------------------
#define AST 40
#define BST 136
#define ABUF (128*AST)          /* 5120 words */
#define BBUF (16*BST)           /* 2176 words */
#define GEMM_SMEM ((2*ABUF + 2*BBUF)*4)   /* 58368 B */

template<int N, bool SCATTER>
__global__ __launch_bounds__(256)
void gemm_mma(const float* __restrict__ A, const float* __restrict__ B,
              const float* __restrict__ bias, float* __restrict__ out)
{
    extern __shared__ __align__(16) unsigned gsm[];
    unsigned* As[2]={gsm, gsm+ABUF};
    unsigned* Bs[2]={gsm+2*ABUF, gsm+2*ABUF+BBUF};

    const int tid=threadIdx.x, lane=tid&31, warp=tid>>5;
    const int g=lane>>2, tg=lane&3;
    const int mtb=(warp>>2)*4, ntb=(warp&3)*4;
    const int bm=blockIdx.y*128, bn=blockIdx.x*128;
    const float* Ab = (SCATTER ? A : (const float*)g_attn) + (size_t)bm*DIMC;
    const float* Bb = B + bn;

    float4 ar[2], br[2];
    float acc[4][4][4];
    #pragma unroll
    for(int i=0;i<4;i++)
      #pragma unroll
      for(int j=0;j<4;j++)
        #pragma unroll
        for(int k=0;k<4;k++) acc[i][j][k]=0.f;

    #pragma unroll
    for(int i=0;i<2;i++){
        int idx=tid+(i<<8);
        ar[i]=*(const float4*)(Ab + (size_t)(idx>>2)*DIMC + ((idx&3)<<2));
        br[i]=*(const float4*)(Bb + (size_t)(idx>>5)*N + ((idx&31)<<2));
    }
    #pragma unroll
    for(int i=0;i<2;i++){
        int idx=tid+(i<<8);
        int r=idx>>2, kc=(idx&3)<<2;
        *(uint4*)&As[0][r*AST+kc] =
            make_uint4(f2tf(ar[i].x),f2tf(ar[i].y),f2tf(ar[i].z),f2tf(ar[i].w));
        int rowb=idx>>5, nc=(idx&31)<<2;
        *(uint4*)&Bs[0][rowb*BST+nc] =
            make_uint4(f2tf(br[i].x),f2tf(br[i].y),f2tf(br[i].z),f2tf(br[i].w));
    }
    __syncthreads();

    const int NT = DIMC/16;
    for(int kt=0;kt<NT;kt++){
        const int buf=kt&1;
        if(kt<NT-1){
            #pragma unroll
            for(int i=0;i<2;i++){
                int idx=tid+(i<<8);
                ar[i]=*(const float4*)(Ab + (size_t)(idx>>2)*DIMC + (kt+1)*16 + ((idx&3)<<2));
                br[i]=*(const float4*)(Bb + (size_t)((kt+1)*16+(idx>>5))*N + ((idx&31)<<2));
            }
        }
        #pragma unroll
        for(int ks=0;ks<2;ks++){
            const int k0=ks*8;
            unsigned af[4][4], bf[4][2];
            #pragma unroll
            for(int mi=0;mi<4;mi++){
                const int m0=(mtb+mi)*16;
                af[mi][0]=As[buf][(m0+g  )*AST+k0+tg  ];
                af[mi][1]=As[buf][(m0+g+8)*AST+k0+tg  ];
                af[mi][2]=As[buf][(m0+g  )*AST+k0+tg+4];
                af[mi][3]=As[buf][(m0+g+8)*AST+k0+tg+4];
            }
            #pragma unroll
            for(int ni=0;ni<4;ni++){
                const int n0=(ntb+ni)*8;
                bf[ni][0]=Bs[buf][(k0+tg  )*BST+n0+g];
                bf[ni][1]=Bs[buf][(k0+tg+4)*BST+n0+g];
            }
            #pragma unroll
            for(int mi=0;mi<4;mi++)
                #pragma unroll
                for(int ni=0;ni<4;ni++)
                    mma8(acc[mi][ni],af[mi],bf[ni]);
        }
        if(kt<NT-1){
            #pragma unroll
            for(int i=0;i<2;i++){
                int idx=tid+(i<<8);
                int r=idx>>2, kc=(idx&3)<<2;
                *(uint4*)&As[buf^1][r*AST+kc] =
                    make_uint4(f2tf(ar[i].x),f2tf(ar[i].y),f2tf(ar[i].z),f2tf(ar[i].w));
                int rowb=idx>>5, nc=(idx&31)<<2;
                *(uint4*)&Bs[buf^1][rowb*BST+nc] =
                    make_uint4(f2tf(br[i].x),f2tf(br[i].y),f2tf(br[i].z),f2tf(br[i].w));
            }
        }
        __syncthreads();
    }

    #pragma unroll
    for(int mi=0;mi<4;mi++){
        #pragma unroll
        for(int ni=0;ni<4;ni++){
            #pragma unroll
            for(int e=0;e<4;e++){
                const int r = bm + (mtb+mi)*16 + g + ((e>=2)?8:0);
                const int c = bn + (ntb+ni)*8 + 2*tg + (e&1);
                const float v = acc[mi][ni][e] + bias[c];
                if(SCATTER){
                    const int b=r>>11, s=r&2047;
                    const int t=c>>10, h=(c>>6)&15, d=c&63;
                    g_qkv[((((size_t)t*BATCH+b)*NHEAD+h)*SEQ+s)*HDIM+d]=v;
                } else {
                    out[(size_t)r*N+c]=v;
                }
            }
        }
    }
}

// ---------------------------------------------------------------------------
// Flash attention: 256 threads, q-tile 128 (8 warps x 16 rows), k-tile 64.
// Natural smem layouts stride 68 (conflict-free scalar frag loads).
// Next K/V tile prefetched into registers during the PV phase.
// ---------------------------------------------------------------------------
#define QKOFF ((size_t)BATCH*NHEAD*SEQ*HDIM)
#define FST 68
#define FLASH_SMEM ((128*FST + 2*64*FST + 8*1024)*4)   /* 102400 B */

__global__ __launch_bounds__(256)
void flash_mma()
{
    extern __shared__ __align__(16) unsigned fsm[];
    unsigned* Qs=fsm;                   // 128*68
    unsigned* Ks=fsm+128*FST;           // 64*68
    unsigned* Vs=Ks+64*FST;             // 64*68
    unsigned* Ps=Vs+64*FST;             // 8*1024
    const int tid=threadIdx.x, lane=tid&31, warp=tid>>5;
    const int g=lane>>2, tg=lane&3;
    const int qb=warp*16;
    const int b=blockIdx.y>>4, h=blockIdx.y&15;
    const int q0=blockIdx.x*128;
    const float* Qg=g_qkv + ((size_t)(b*NHEAD+h))*SEQ*HDIM;
    const float* Kg=Qg + QKOFF;
    const float* Vg=Kg + QKOFF;
    unsigned* Pw = Ps + warp*1024;

    float4 kr[4], vr[4];
    // issue K/V tile-0 loads first (longest latency)
    #pragma unroll
    for(int i=0;i<4;i++){
        int idx=tid+(i<<8);
        int r=idx>>4, c4=(idx&15)<<2;
        kr[i]=*(const float4*)(Kg+(size_t)r*HDIM+c4);
        vr[i]=*(const float4*)(Vg+(size_t)r*HDIM+c4);
    }
    // Q (scale folded in)
    #pragma unroll
    for(int i=0;i<8;i++){
        int idx=tid+(i<<8);
        int r=idx>>4, c4=(idx&15)<<2;
        float4 q4=*(const float4*)(Qg+(size_t)(q0+r)*HDIM+c4);
        *(uint4*)&Qs[r*FST+c4] =
            make_uint4(f2tf(q4.x*0.125f),f2tf(q4.y*0.125f),
                       f2tf(q4.z*0.125f),f2tf(q4.w*0.125f));
    }
    #pragma unroll
    for(int i=0;i<4;i++){
        int idx=tid+(i<<8);
        int r=idx>>4, c4=(idx&15)<<2;
        *(uint4*)&Ks[r*FST+c4]=make_uint4(f2tf(kr[i].x),f2tf(kr[i].y),f2tf(kr[i].z),f2tf(kr[i].w));
        *(uint4*)&Vs[r*FST+c4]=make_uint4(f2tf(vr[i].x),f2tf(vr[i].y),f2tf(vr[i].z),f2tf(vr[i].w));
    }
    __syncthreads();

    float oc[8][4];
    #pragma unroll
    for(int i=0;i<8;i++)
        #pragma unroll
        for(int j=0;j<4;j++) oc[i][j]=0.f;
    float m0=-1e30f, m1=-1e30f, l0=0.f, l1=0.f;

    const int NKT = SEQ/64;
    for(int kt=0;kt<NKT;kt++){
        // S = Q @ K^T
        float sc[8][4];
        #pragma unroll
        for(int i=0;i<8;i++)
            #pragma unroll
            for(int j=0;j<4;j++) sc[i][j]=0.f;
        #pragma unroll
        for(int ks=0;ks<8;ks++){
            const int k0=ks*8;
            unsigned aq[4];
            aq[0]=Qs[(qb+g  )*FST+k0+tg  ];
            aq[1]=Qs[(qb+g+8)*FST+k0+tg  ];
            aq[2]=Qs[(qb+g  )*FST+k0+tg+4];
            aq[3]=Qs[(qb+g+8)*FST+k0+tg+4];
            #pragma unroll
            for(int ni=0;ni<8;ni++){
                unsigned bf[2];
                bf[0]=Ks[(ni*8+g)*FST+k0+tg  ];
                bf[1]=Ks[(ni*8+g)*FST+k0+tg+4];
                mma8(sc[ni],aq,bf);
            }
        }

        // online softmax
        float mx0=-1e30f, mx1=-1e30f;
        #pragma unroll
        for(int ni=0;ni<8;ni++){
            mx0=fmaxf(mx0,fmaxf(sc[ni][0],sc[ni][1]));
            mx1=fmaxf(mx1,fmaxf(sc[ni][2],sc[ni][3]));
        }
        mx0=fmaxf(mx0,__shfl_xor_sync(0xffffffffu,mx0,1));
        mx0=fmaxf(mx0,__shfl_xor_sync(0xffffffffu,mx0,2));
        mx1=fmaxf(mx1,__shfl_xor_sync(0xffffffffu,mx1,1));
        mx1=fmaxf(mx1,__shfl_xor_sync(0xffffffffu,mx1,2));
        const float nm0=fmaxf(m0,mx0), nm1=fmaxf(m1,mx1);
        const float a0=__expf(m0-nm0), a1=__expf(m1-nm1);
        m0=nm0; m1=nm1;
        float s0=0.f, s1=0.f;
        #pragma unroll
        for(int ni=0;ni<8;ni++){
            sc[ni][0]=__expf(sc[ni][0]-nm0); sc[ni][1]=__expf(sc[ni][1]-nm0);
            sc[ni][2]=__expf(sc[ni][2]-nm1); sc[ni][3]=__expf(sc[ni][3]-nm1);
            s0+=sc[ni][0]+sc[ni][1];
            s1+=sc[ni][2]+sc[ni][3];
        }
        s0+=__shfl_xor_sync(0xffffffffu,s0,1); s0+=__shfl_xor_sync(0xffffffffu,s0,2);
        s1+=__shfl_xor_sync(0xffffffffu,s1,1); s1+=__shfl_xor_sync(0xffffffffu,s1,2);
        l0=l0*a0+s0; l1=l1*a1+s1;

        // P -> per-warp fragment buffer
        #pragma unroll
        for(int ni=0;ni<8;ni++){
            unsigned* pp=&Pw[(ni*32 + g*4 + ((2*tg)&3))*4 + 2*(tg>>1)];
            *(uint2*)pp    =make_uint2(f2tf(sc[ni][0]), f2tf(sc[ni][2]));
            *(uint2*)(pp+4)=make_uint2(f2tf(sc[ni][1]), f2tf(sc[ni][3]));
        }
        __syncwarp();

        // prefetch next K/V tile (overlaps PV phase)
        if(kt<NKT-1){
            #pragma unroll
            for(int i=0;i<4;i++){
                int idx=tid+(i<<8);
                int r=idx>>4, c4=(idx&15)<<2;
                kr[i]=*(const float4*)(Kg+(size_t)((kt+1)*64+r)*HDIM+c4);
                vr[i]=*(const float4*)(Vg+(size_t)((kt+1)*64+r)*HDIM+c4);
            }
        }

        #pragma unroll
        for(int di=0;di<8;di++){
            oc[di][0]*=a0; oc[di][1]*=a0; oc[di][2]*=a1; oc[di][3]*=a1;
        }
        // O += P @ V
        #pragma unroll
        for(int ks=0;ks<8;ks++){
            const int k0=ks*8;
            uint4 af4=*(const uint4*)&Pw[ks*128 + lane*4];
            const unsigned* AF=(const unsigned*)&af4;
            #pragma unroll
            for(int di=0;di<8;di++){
                unsigned bf[2];
                bf[0]=Vs[(k0+tg  )*FST+di*8+g];
                bf[1]=Vs[(k0+tg+4)*FST+di*8+g];
                mma8(oc[di],AF,bf);
            }
        }
        __syncthreads();    // PV reads of Ks/Vs done
        if(kt<NKT-1){
            #pragma unroll
            for(int i=0;i<4;i++){
                int idx=tid+(i<<8);
                int r=idx>>4, c4=(idx&15)<<2;
                *(uint4*)&Ks[r*FST+c4]=make_uint4(f2tf(kr[i].x),f2tf(kr[i].y),f2tf(kr[i].z),f2tf(kr[i].w));
                *(uint4*)&Vs[r*FST+c4]=make_uint4(f2tf(vr[i].x),f2tf(vr[i].y),f2tf(vr[i].z),f2tf(vr[i].w));
            }
            __syncthreads();
        }
    }

    const float i0=1.f/l0, i1=1.f/l1;
    const int r0=q0+qb+g, r1=r0+8;
    float* O0=&g_attn[((size_t)(b*SEQ)+r0)*DIMC + h*HDIM];
    float* O1=&g_attn[((size_t)(b*SEQ)+r1)*DIMC + h*HDIM];
    #pragma unroll
    for(int di=0;di<8;di++){
        const int c=di*8+2*tg;
        *(float2*)&O0[c]=make_float2(oc[di][0]*i0, oc[di][1]*i0);
        *(float2*)&O1[c]=make_float2(oc[di][2]*i1, oc[di][3]*i1);
    }
}

// ---------------------------------------------------------------------------
extern "C" void kernel_launch(void* const* d_in, const int* in_sizes, int n_in,
                              void* d_out, int out_size)
{
    const float* x     = (const float*)d_in[0];
    const float* Wqkv  = (const float*)d_in[1];
    const float* bqkv  = (const float*)d_in[2];
    const float* Wproj = (const float*)d_in[3];
    const float* bproj = (const float*)d_in[4];
    float* out = (float*)d_out;

    static int inited = 0;
    if(!inited){
        cudaFuncSetAttribute(gemm_mma<NQKV,true>,  cudaFuncAttributeMaxDynamicSharedMemorySize, GEMM_SMEM);
        cudaFuncSetAttribute(gemm_mma<DIMC,false>, cudaFuncAttributeMaxDynamicSharedMemorySize, GEMM_SMEM);
        cudaFuncSetAttribute(flash_mma, cudaFuncAttributeMaxDynamicSharedMemorySize, FLASH_SMEM);
        inited = 1;
    }

    dim3 g1(NQKV/128, MTOT/128);   // (24, 64)
    gemm_mma<NQKV, true><<<g1, 256, GEMM_SMEM>>>(x, Wqkv, bqkv, nullptr);

    dim3 g2(SEQ/128, BATCH*NHEAD); // (16, 64)
    flash_mma<<<g2, 256, FLASH_SMEM>>>();

    dim3 g3(DIMC/128, MTOT/128);   // (8, 64)
    gemm_mma<DIMC, false><<<g3, 256, GEMM_SMEM>>>(Wproj, Wproj, bproj, out);
}